// round 3
// baseline (speedup 1.0000x reference)
#include <cuda_runtime.h>
#include <math.h>

#define BB 2048
#define LL 200
#define CC 100
#define D_ID 64
#define D_TXT 128
#define D_CTX 128
#define KW 5
#define VV 2000
#define D_IN 192
#define NH 128

// ---------------- scratch (static device arrays; no allocation) ----------------
__device__ float g_XK[BB * KW * D_IN];          // gathered window inputs
__device__ float g_IG[BB * KW * 3 * D_CTX];     // precomputed input gates (x@W_ih.T + b_ih)
__device__ float g_H0[BB * D_CTX];
__device__ float g_H1[BB * D_CTX];
__device__ float g_last_text[BB * D_TXT];
__device__ float g_last_id[BB * D_ID];
__device__ int   g_last_item[BB];
__device__ float g_base_t[BB * NH];
__device__ float g_base_i[BB * NH];
__device__ float g_alpha[BB * 3];
__device__ float g_logits_t[BB * CC];
__device__ float g_logits_i[BB * CC];

// ---------------- 1) gather window + last-step features, zero H0 ----------------
__global__ void prep_kernel(const int* __restrict__ seq_items,
                            const float* __restrict__ seq_id,
                            const float* __restrict__ seq_txt,
                            const int* __restrict__ lengths) {
    int b = blockIdx.x, t = threadIdx.x;     // 192 threads
    int len = lengths[b];
    int start = len - KW, last = len - 1;
#pragma unroll
    for (int k = 0; k < KW; k++) {
        float v;
        if (t < D_ID) v = seq_id[(b * LL + start + k) * D_ID + t];
        else          v = seq_txt[(b * LL + start + k) * D_TXT + (t - D_ID)];
        g_XK[(b * KW + k) * D_IN + t] = v;
    }
    if (t < D_ID)  g_last_id[b * D_ID + t]   = seq_id[(b * LL + last) * D_ID + t];
    if (t < D_TXT) g_last_text[b * D_TXT + t] = seq_txt[(b * LL + last) * D_TXT + t];
    if (t < D_CTX) g_H0[b * D_CTX + t] = 0.f;
    if (t == 0)    g_last_item[b] = seq_items[b * LL + last];
}

// ---------------- 2) i-gates GEMM: IG[M=10240, N=384] = XK[M,192] @ W_ih.T + b_ih ----------------
__global__ __launch_bounds__(256, 2) void ih_gemm(const float* __restrict__ Wih,
                                                  const float* __restrict__ bih) {
    __shared__ float As[128][33];
    __shared__ float Bs[64][33];
    int row0 = blockIdx.x * 128;
    int col0 = blockIdx.y * 64;
    int tid = threadIdx.x, tx = tid & 15, ty = tid >> 4;
    float acc[8][4];
#pragma unroll
    for (int i = 0; i < 8; i++)
#pragma unroll
        for (int j = 0; j < 4; j++) acc[i][j] = 0.f;

    for (int k0 = 0; k0 < D_IN; k0 += 32) {
        for (int i = tid; i < 128 * 32; i += 256)
            As[i >> 5][i & 31] = g_XK[(row0 + (i >> 5)) * D_IN + k0 + (i & 31)];
        for (int i = tid; i < 64 * 32; i += 256)
            Bs[i >> 5][i & 31] = Wih[(col0 + (i >> 5)) * D_IN + k0 + (i & 31)];
        __syncthreads();
#pragma unroll
        for (int k = 0; k < 32; k++) {
            float a[8], w[4];
#pragma unroll
            for (int i = 0; i < 8; i++) a[i] = As[ty + 16 * i][k];
#pragma unroll
            for (int j = 0; j < 4; j++) w[j] = Bs[tx + 16 * j][k];
#pragma unroll
            for (int i = 0; i < 8; i++)
#pragma unroll
                for (int j = 0; j < 4; j++) acc[i][j] = fmaf(a[i], w[j], acc[i][j]);
        }
        __syncthreads();
    }
#pragma unroll
    for (int j = 0; j < 4; j++) {
        int col = col0 + tx + 16 * j;
        float bv = bih[col];
#pragma unroll
        for (int i = 0; i < 8; i++)
            g_IG[(row0 + ty + 16 * i) * (3 * D_CTX) + col] = acc[i][j] + bv;
    }
}

// ---------------- 3) one GRU step: h-gates GEMM + pointwise update (double-buffered H) ----------------
__global__ __launch_bounds__(128) void gru_step(const float* __restrict__ Whh,
                                                const float* __restrict__ bhh,
                                                int step) {
    __shared__ float Ws[96][33];   // 3 gate strips x 32 hidden units
    __shared__ float Hs[32][33];
    const float* hin = (step & 1) ? g_H1 : g_H0;
    float* hout      = (step & 1) ? g_H0 : g_H1;
    int row0 = blockIdx.x * 32;
    int jj0  = blockIdx.y * 32;
    int tid = threadIdx.x, tx = tid & 15, ty = tid >> 4;   // ty < 8
    float acc[3][4][2];
#pragma unroll
    for (int g = 0; g < 3; g++)
#pragma unroll
        for (int i = 0; i < 4; i++)
#pragma unroll
            for (int jq = 0; jq < 2; jq++) acc[g][i][jq] = 0.f;

    for (int k0 = 0; k0 < D_CTX; k0 += 32) {
        for (int i = tid; i < 96 * 32; i += 128) {
            int r = i >> 5, k = i & 31;
            int g = r >> 5, jl = r & 31;
            Ws[r][k] = Whh[(g * 128 + jj0 + jl) * D_CTX + k0 + k];
        }
        for (int i = tid; i < 32 * 32; i += 128) {
            int r = i >> 5, k = i & 31;
            Hs[r][k] = hin[(row0 + r) * D_CTX + k0 + k];
        }
        __syncthreads();
#pragma unroll
        for (int k = 0; k < 32; k++) {
            float h4[4];
#pragma unroll
            for (int i = 0; i < 4; i++) h4[i] = Hs[ty + 8 * i][k];
#pragma unroll
            for (int jq = 0; jq < 2; jq++) {
                int jl = tx + 16 * jq;
                float wr = Ws[jl][k], wz = Ws[32 + jl][k], wn = Ws[64 + jl][k];
#pragma unroll
                for (int i = 0; i < 4; i++) {
                    acc[0][i][jq] = fmaf(h4[i], wr, acc[0][i][jq]);
                    acc[1][i][jq] = fmaf(h4[i], wz, acc[1][i][jq]);
                    acc[2][i][jq] = fmaf(h4[i], wn, acc[2][i][jq]);
                }
            }
        }
        __syncthreads();
    }
#pragma unroll
    for (int jq = 0; jq < 2; jq++) {
        int jj = jj0 + tx + 16 * jq;
        float br = bhh[jj], bz = bhh[128 + jj], bn = bhh[256 + jj];
#pragma unroll
        for (int i = 0; i < 4; i++) {
            int row = row0 + ty + 8 * i;
            const float* ig = &g_IG[(row * KW + step) * 384];
            float r = 1.f / (1.f + expf(-(ig[jj]       + acc[0][i][jq] + br)));
            float z = 1.f / (1.f + expf(-(ig[128 + jj] + acc[1][i][jq] + bz)));
            float n = tanhf(ig[256 + jj] + r * (acc[2][i][jq] + bn));
            float hold = hin[row * D_CTX + jj];
            hout[row * D_CTX + jj] = (1.f - z) * n + z * hold;
        }
    }
}

// ---------------- 4) per-row scorer bases: base = W1_src@e_src + W1_h@h + b1 ----------------
__global__ __launch_bounds__(128) void posth_kernel(const float* __restrict__ Wt1,
                                                    const float* __restrict__ bt1,
                                                    const float* __restrict__ Wi1,
                                                    const float* __restrict__ bi1) {
    __shared__ float Xs[32][33];
    __shared__ float Ws[64][33];
    int row0 = blockIdx.x * 32;
    int h0 = blockIdx.y * 64;
    int tid = threadIdx.x, tx = tid & 15, ty = tid >> 4;   // ty < 8
    float acc[4][4];

    // ---- phase A: base_t (K = 128 text + 128 h) ----
#pragma unroll
    for (int i = 0; i < 4; i++)
#pragma unroll
        for (int j = 0; j < 4; j++) acc[i][j] = 0.f;
    for (int k0 = 0; k0 < 256; k0 += 32) {
        for (int i = tid; i < 32 * 32; i += 128) {
            int r = i >> 5, k = i & 31, kg = k0 + k;
            Xs[r][k] = (kg < 128) ? g_last_text[(row0 + r) * 128 + kg]
                                  : g_H1[(row0 + r) * 128 + (kg - 128)];
        }
        for (int i = tid; i < 64 * 32; i += 128) {
            int r = i >> 5, k = i & 31, kg = k0 + k;
            Ws[r][k] = (kg < 128) ? Wt1[(h0 + r) * 384 + kg]
                                  : Wt1[(h0 + r) * 384 + 128 + kg];   // 256 + (kg-128)
        }
        __syncthreads();
#pragma unroll
        for (int k = 0; k < 32; k++) {
            float a[4], w[4];
#pragma unroll
            for (int i = 0; i < 4; i++) a[i] = Xs[ty + 8 * i][k];
#pragma unroll
            for (int j = 0; j < 4; j++) w[j] = Ws[tx + 16 * j][k];
#pragma unroll
            for (int i = 0; i < 4; i++)
#pragma unroll
                for (int j = 0; j < 4; j++) acc[i][j] = fmaf(a[i], w[j], acc[i][j]);
        }
        __syncthreads();
    }
#pragma unroll
    for (int j = 0; j < 4; j++) {
        int h = h0 + tx + 16 * j;
        float bv = bt1[h];
#pragma unroll
        for (int i = 0; i < 4; i++)
            g_base_t[(row0 + ty + 8 * i) * NH + h] = acc[i][j] + bv;
    }
    __syncthreads();

    // ---- phase B: base_i (K = 64 id + 128 h) ----
#pragma unroll
    for (int i = 0; i < 4; i++)
#pragma unroll
        for (int j = 0; j < 4; j++) acc[i][j] = 0.f;
    for (int k0 = 0; k0 < 192; k0 += 32) {
        for (int i = tid; i < 32 * 32; i += 128) {
            int r = i >> 5, k = i & 31, kg = k0 + k;
            Xs[r][k] = (kg < 64) ? g_last_id[(row0 + r) * 64 + kg]
                                 : g_H1[(row0 + r) * 128 + (kg - 64)];
        }
        for (int i = tid; i < 64 * 32; i += 128) {
            int r = i >> 5, k = i & 31, kg = k0 + k;
            Ws[r][k] = (kg < 64) ? Wi1[(h0 + r) * 256 + kg]
                                 : Wi1[(h0 + r) * 256 + 64 + kg];    // 128 + (kg-64)
        }
        __syncthreads();
#pragma unroll
        for (int k = 0; k < 32; k++) {
            float a[4], w[4];
#pragma unroll
            for (int i = 0; i < 4; i++) a[i] = Xs[ty + 8 * i][k];
#pragma unroll
            for (int j = 0; j < 4; j++) w[j] = Ws[tx + 16 * j][k];
#pragma unroll
            for (int i = 0; i < 4; i++)
#pragma unroll
                for (int j = 0; j < 4; j++) acc[i][j] = fmaf(a[i], w[j], acc[i][j]);
        }
        __syncthreads();
    }
#pragma unroll
    for (int j = 0; j < 4; j++) {
        int h = h0 + tx + 16 * j;
        float bv = bi1[h];
#pragma unroll
        for (int i = 0; i < 4; i++)
            g_base_i[(row0 + ty + 8 * i) * NH + h] = acc[i][j] + bv;
    }
}

// ---------------- 5) mixture gate alpha = softmax(Wa2 @ relu(Wa1 @ h + ba1) + ba2) ----------------
__global__ void alpha_kernel(const float* __restrict__ Wa1, const float* __restrict__ ba1,
                             const float* __restrict__ Wa2, const float* __restrict__ ba2) {
    __shared__ float hs[128];
    __shared__ float a1s[64];
    int b = blockIdx.x, t = threadIdx.x;   // 64 threads
    hs[t]      = g_H1[b * 128 + t];
    hs[64 + t] = g_H1[b * 128 + 64 + t];
    __syncthreads();
    float s = ba1[t];
#pragma unroll 4
    for (int d = 0; d < 128; d++) s = fmaf(Wa1[t * 128 + d], hs[d], s);
    a1s[t] = fmaxf(s, 0.f);
    __syncthreads();
    if (t == 0) {
        float lg[3];
#pragma unroll
        for (int g = 0; g < 3; g++) {
            float x = ba2[g];
            for (int d = 0; d < 64; d++) x = fmaf(Wa2[g * 64 + d], a1s[d], x);
            lg[g] = x;
        }
        float m = fmaxf(lg[0], fmaxf(lg[1], lg[2]));
        float e0 = expf(lg[0] - m), e1 = expf(lg[1] - m), e2 = expf(lg[2] - m);
        float ss = e0 + e1 + e2;
        g_alpha[b * 3 + 0] = e0 / ss;
        g_alpha[b * 3 + 1] = e1 / ss;
        g_alpha[b * 3 + 2] = e2 / ss;
    }
}

// ---------------- 6) bulk scorer GEMM + relu + dot(w2) epilogue ----------------
// logits[row] = b2 + sum_h relu(base[b][h] + sum_k A[row,k]*W[h,k]) * w2[h]
template <int KD, int WS, bool TEXT>
__global__ __launch_bounds__(256, 2) void scorer_kernel(const float* __restrict__ A,
                                                        const float* __restrict__ W,
                                                        const float* __restrict__ w2,
                                                        const float* __restrict__ b2p) {
    __shared__ float As[128][33];
    __shared__ float Ws[128][33];
    const float* base = TEXT ? g_base_t : g_base_i;
    float* outL       = TEXT ? g_logits_t : g_logits_i;
    int row0 = blockIdx.x * 128;
    int tid = threadIdx.x, tx = tid & 15, ty = tid >> 4;
    float acc[8][8];
#pragma unroll
    for (int i = 0; i < 8; i++)
#pragma unroll
        for (int j = 0; j < 8; j++) acc[i][j] = 0.f;

    for (int k0 = 0; k0 < KD; k0 += 32) {
        for (int i = tid; i < 128 * 32; i += 256)
            As[i >> 5][i & 31] = A[(row0 + (i >> 5)) * KD + k0 + (i & 31)];
        for (int i = tid; i < 128 * 32; i += 256)
            Ws[i >> 5][i & 31] = W[(i >> 5) * WS + k0 + (i & 31)];
        __syncthreads();
#pragma unroll
        for (int k = 0; k < 32; k++) {
            float a[8], w[8];
#pragma unroll
            for (int i = 0; i < 8; i++) a[i] = As[ty + 16 * i][k];
#pragma unroll
            for (int j = 0; j < 8; j++) w[j] = Ws[tx + 16 * j][k];
#pragma unroll
            for (int i = 0; i < 8; i++)
#pragma unroll
                for (int j = 0; j < 8; j++) acc[i][j] = fmaf(a[i], w[j], acc[i][j]);
        }
        __syncthreads();
    }
    float b2 = b2p[0];
    float w2r[8];
#pragma unroll
    for (int j = 0; j < 8; j++) w2r[j] = w2[tx + 16 * j];
#pragma unroll
    for (int i = 0; i < 8; i++) {
        int row = row0 + ty + 16 * i;
        int b = row / CC;
        const float* bp = base + b * NH;
        float p = 0.f;
#pragma unroll
        for (int j = 0; j < 8; j++) {
            float v = acc[i][j] + bp[tx + 16 * j];
            v = fmaxf(v, 0.f);
            p = fmaf(v, w2r[j], p);
        }
        p += __shfl_xor_sync(0xffffffff, p, 8);
        p += __shfl_xor_sync(0xffffffff, p, 4);
        p += __shfl_xor_sync(0xffffffff, p, 2);
        p += __shfl_xor_sync(0xffffffff, p, 1);
        if (tx == 0) outL[row] = p + b2;
    }
}

// ---------------- 7) three softmaxes + mixture + normalize ----------------
__device__ __forceinline__ float blkmax(float v, float* sm) {
    int t = threadIdx.x;
    sm[t] = v; __syncthreads();
#pragma unroll
    for (int s = 64; s > 0; s >>= 1) {
        if (t < s) sm[t] = fmaxf(sm[t], sm[t + s]);
        __syncthreads();
    }
    float r = sm[0]; __syncthreads();
    return r;
}
__device__ __forceinline__ float blksum(float v, float* sm) {
    int t = threadIdx.x;
    sm[t] = v; __syncthreads();
#pragma unroll
    for (int s = 64; s > 0; s >>= 1) {
        if (t < s) sm[t] = sm[t] + sm[t + s];
        __syncthreads();
    }
    float r = sm[0]; __syncthreads();
    return r;
}

__global__ void finalize_kernel(const int* __restrict__ cand_ids,
                                const float* __restrict__ co_table,
                                const float* __restrict__ beta_c,
                                const float* __restrict__ logT_c,
                                const float* __restrict__ logT_t,
                                const float* __restrict__ logT_id,
                                float* __restrict__ out) {
    __shared__ float sm[128];
    int b = blockIdx.x, t = threadIdx.x;   // 128 threads
    float itc = expf(-logT_c[0]) * beta_c[0];
    float itt = expf(-logT_t[0]);
    float iti = expf(-logT_id[0]);
    float vc = -1e30f, vt = -1e30f, vi = -1e30f;
    if (t < CC) {
        int cid = cand_ids[b * CC + t];
        vc = co_table[g_last_item[b] * VV + cid] * itc;
        vt = g_logits_t[b * CC + t] * itt;
        vi = g_logits_i[b * CC + t] * iti;
    }
    float mc = blkmax(vc, sm);
    float mt = blkmax(vt, sm);
    float mi = blkmax(vi, sm);
    float ec = (t < CC) ? expf(vc - mc) : 0.f;
    float et = (t < CC) ? expf(vt - mt) : 0.f;
    float ei = (t < CC) ? expf(vi - mi) : 0.f;
    float sc = blksum(ec, sm);
    float st = blksum(et, sm);
    float si = blksum(ei, sm);
    float a0 = g_alpha[b * 3 + 0], a1 = g_alpha[b * 3 + 1], a2 = g_alpha[b * 3 + 2];
    float mix = 0.f;
    if (t < CC) {
        // P_stable is softmax of a row-constant vector => exactly 1/C
        mix = a0 * (ec / sc) + a1 * (et / st) + a2 * (ei / si) + (1.0f / CC);
        mix = fmaxf(mix, 1e-12f);
    }
    float tot = blksum(mix, sm);
    if (t < CC) out[b * CC + t] = mix / tot;
}

// ---------------- launch ----------------
extern "C" void kernel_launch(void* const* d_in, const int* in_sizes, int n_in,
                              void* d_out, int out_size) {
    const int*   seq_items = (const int*)d_in[0];
    const float* seq_id    = (const float*)d_in[1];
    const float* seq_txt   = (const float*)d_in[2];
    const int*   lengths   = (const int*)d_in[3];
    const int*   cand_ids  = (const int*)d_in[4];
    const float* cand_id_e = (const float*)d_in[5];
    const float* cand_tx_e = (const float*)d_in[6];
    const float* co_table  = (const float*)d_in[7];
    const float* W_ih = (const float*)d_in[8];
    const float* W_hh = (const float*)d_in[9];
    const float* b_ih = (const float*)d_in[10];
    const float* b_hh = (const float*)d_in[11];
    const float* Wt1  = (const float*)d_in[12];
    const float* bt1  = (const float*)d_in[13];
    const float* Wt2  = (const float*)d_in[14];
    const float* bt2  = (const float*)d_in[15];
    const float* Wi1  = (const float*)d_in[16];
    const float* bi1  = (const float*)d_in[17];
    const float* Wi2  = (const float*)d_in[18];
    const float* bi2  = (const float*)d_in[19];
    const float* Wa1  = (const float*)d_in[20];
    const float* ba1  = (const float*)d_in[21];
    const float* Wa2  = (const float*)d_in[22];
    const float* ba2  = (const float*)d_in[23];
    // d_in[24] (Wstab) is dead: softmax of a row-constant vector is uniform.
    const float* beta_c  = (const float*)d_in[25];
    const float* logT_c  = (const float*)d_in[26];
    const float* logT_t  = (const float*)d_in[27];
    const float* logT_id = (const float*)d_in[28];
    float* out = (float*)d_out;

    prep_kernel<<<BB, 192>>>(seq_items, seq_id, seq_txt, lengths);
    ih_gemm<<<dim3(80, 6), 256>>>(W_ih, b_ih);
    for (int s = 0; s < KW; s++)
        gru_step<<<dim3(64, 4), 128>>>(W_hh, b_hh, s);
    posth_kernel<<<dim3(64, 2), 128>>>(Wt1, bt1, Wi1, bi1);
    alpha_kernel<<<BB, 64>>>(Wa1, ba1, Wa2, ba2);
    scorer_kernel<128, 384, true><<<1600, 256>>>(cand_tx_e, Wt1 + 128, Wt2, bt2);
    scorer_kernel<64, 256, false><<<1600, 256>>>(cand_id_e, Wi1 + 64, Wi2, bi2);
    finalize_kernel<<<BB, 128>>>(cand_ids, co_table, beta_c, logT_c, logT_t, logT_id, out);
}

// round 4
// speedup vs baseline: 1.0976x; 1.0976x over previous
#include <cuda_runtime.h>
#include <math.h>

#define BB 2048
#define LL 200
#define CC 100
#define D_ID 64
#define D_TXT 128
#define D_CTX 128
#define KW 5
#define VV 2000
#define D_IN 192
#define NH 128

typedef unsigned long long ull;

// ---------------- scratch (static device arrays; no allocation) ----------------
__device__ float g_XK[BB * KW * D_IN];
__device__ float g_IG[BB * KW * 3 * D_CTX];
__device__ float g_WhhT[D_CTX * 3 * D_CTX];    // [128][384] k-major transpose of W_hh
__device__ float g_H1[BB * D_CTX];
__device__ float g_last_text[BB * D_TXT];
__device__ float g_last_id[BB * D_ID];
__device__ int   g_last_item[BB];
__device__ float g_base_t[BB * NH];
__device__ float g_base_i[BB * NH];
__device__ float g_alpha[BB * 3];
__device__ float g_logits_t[BB * CC];
__device__ float g_logits_i[BB * CC];

// ---------------- 1) gather window + last-step features ----------------
__global__ void prep_kernel(const int* __restrict__ seq_items,
                            const float* __restrict__ seq_id,
                            const float* __restrict__ seq_txt,
                            const int* __restrict__ lengths) {
    int b = blockIdx.x, t = threadIdx.x;     // 192 threads
    int len = lengths[b];
    int start = len - KW, last = len - 1;
#pragma unroll
    for (int k = 0; k < KW; k++) {
        float v;
        if (t < D_ID) v = seq_id[(b * LL + start + k) * D_ID + t];
        else          v = seq_txt[(b * LL + start + k) * D_TXT + (t - D_ID)];
        g_XK[(b * KW + k) * D_IN + t] = v;
    }
    if (t < D_ID)  g_last_id[b * D_ID + t]   = seq_id[(b * LL + last) * D_ID + t];
    if (t < D_TXT) g_last_text[b * D_TXT + t] = seq_txt[(b * LL + last) * D_TXT + t];
    if (t == 0)    g_last_item[b] = seq_items[b * LL + last];
}

// ---------------- 1b) transpose W_hh [384][128] -> g_WhhT [128][384] ----------------
__global__ void transpose_whh(const float* __restrict__ Whh) {
    __shared__ float t[32][33];
    int bx = blockIdx.x, by = blockIdx.y;    // bx: 12 tiles over 384, by: 4 over 128
    int x = threadIdx.x, y = threadIdx.y;    // 32 x 8
#pragma unroll
    for (int i = 0; i < 32; i += 8)
        t[y + i][x] = Whh[(bx * 32 + y + i) * D_CTX + by * 32 + x];
    __syncthreads();
#pragma unroll
    for (int i = 0; i < 32; i += 8)
        g_WhhT[(by * 32 + y + i) * 384 + bx * 32 + x] = t[x][y + i];
}

// ---------------- 2) i-gates GEMM: IG[10240,384] = XK[10240,192] @ W_ih.T + b_ih ----------------
__global__ __launch_bounds__(256, 2) void ih_gemm(const float* __restrict__ Wih,
                                                  const float* __restrict__ bih) {
    __shared__ float As[128][33];
    __shared__ float Bs[64][33];
    int row0 = blockIdx.x * 128;
    int col0 = blockIdx.y * 64;
    int tid = threadIdx.x, tx = tid & 15, ty = tid >> 4;
    float acc[8][4];
#pragma unroll
    for (int i = 0; i < 8; i++)
#pragma unroll
        for (int j = 0; j < 4; j++) acc[i][j] = 0.f;

    for (int k0 = 0; k0 < D_IN; k0 += 32) {
        for (int i = tid; i < 128 * 32; i += 256)
            As[i >> 5][i & 31] = g_XK[(row0 + (i >> 5)) * D_IN + k0 + (i & 31)];
        for (int i = tid; i < 64 * 32; i += 256)
            Bs[i >> 5][i & 31] = Wih[(col0 + (i >> 5)) * D_IN + k0 + (i & 31)];
        __syncthreads();
#pragma unroll
        for (int k = 0; k < 32; k++) {
            float a[8], w[4];
#pragma unroll
            for (int i = 0; i < 8; i++) a[i] = As[ty + 16 * i][k];
#pragma unroll
            for (int j = 0; j < 4; j++) w[j] = Bs[tx + 16 * j][k];
#pragma unroll
            for (int i = 0; i < 8; i++)
#pragma unroll
                for (int j = 0; j < 4; j++) acc[i][j] = fmaf(a[i], w[j], acc[i][j]);
        }
        __syncthreads();
    }
#pragma unroll
    for (int j = 0; j < 4; j++) {
        int col = col0 + tx + 16 * j;
        float bv = bih[col];
#pragma unroll
        for (int i = 0; i < 8; i++)
            g_IG[(row0 + ty + 16 * i) * (3 * D_CTX) + col] = acc[i][j] + bv;
    }
}

// ---------------- 3) fused GRU: all 5 steps, W_hh resident in shared ----------------
// grid = 128 blocks x 16 rows; block = 256 threads (tx 0..15 -> 8 units, ty 0..15 -> row)
extern __shared__ float smem_dyn[];
__global__ __launch_bounds__(256) void gru_fused(const float* __restrict__ bhh) {
    float* Ws = smem_dyn;                 // [128][384], Ws[k][g*128+j]
    float* Hs = smem_dyn + 128 * 384;     // [16][128]
    int tid = threadIdx.x;
    int tx = tid & 15, ty = tid >> 4;
    int row0 = blockIdx.x * 16;
    int row = row0 + ty;

    // load transposed W_hh into shared (float4, coalesced, conflict-free)
    {
        const float4* src = (const float4*)g_WhhT;
        float4* dst = (float4*)Ws;
        for (int i = tid; i < 128 * 384 / 4; i += 256) dst[i] = src[i];
    }
    for (int i = tid; i < 16 * 128; i += 256) Hs[i] = 0.f;

    // biases for this thread's 8 units
    float br[8], bz[8], bn[8];
#pragma unroll
    for (int u = 0; u < 8; u++) {
        br[u] = bhh[8 * tx + u];
        bz[u] = bhh[128 + 8 * tx + u];
        bn[u] = bhh[256 + 8 * tx + u];
    }
    __syncthreads();

    for (int s = 0; s < KW; s++) {
        float aR[8], aZ[8], aN[8];
#pragma unroll
        for (int u = 0; u < 8; u++) { aR[u] = 0.f; aZ[u] = 0.f; aN[u] = 0.f; }
#pragma unroll 4
        for (int k = 0; k < 128; k++) {
            float h = Hs[ty * 128 + k];
            const float* w = Ws + k * 384;
            float4 r0 = *(const float4*)(w + 8 * tx);
            float4 r1 = *(const float4*)(w + 8 * tx + 4);
            float4 z0 = *(const float4*)(w + 128 + 8 * tx);
            float4 z1 = *(const float4*)(w + 128 + 8 * tx + 4);
            float4 n0 = *(const float4*)(w + 256 + 8 * tx);
            float4 n1 = *(const float4*)(w + 256 + 8 * tx + 4);
            aR[0] = fmaf(h, r0.x, aR[0]); aR[1] = fmaf(h, r0.y, aR[1]);
            aR[2] = fmaf(h, r0.z, aR[2]); aR[3] = fmaf(h, r0.w, aR[3]);
            aR[4] = fmaf(h, r1.x, aR[4]); aR[5] = fmaf(h, r1.y, aR[5]);
            aR[6] = fmaf(h, r1.z, aR[6]); aR[7] = fmaf(h, r1.w, aR[7]);
            aZ[0] = fmaf(h, z0.x, aZ[0]); aZ[1] = fmaf(h, z0.y, aZ[1]);
            aZ[2] = fmaf(h, z0.z, aZ[2]); aZ[3] = fmaf(h, z0.w, aZ[3]);
            aZ[4] = fmaf(h, z1.x, aZ[4]); aZ[5] = fmaf(h, z1.y, aZ[5]);
            aZ[6] = fmaf(h, z1.z, aZ[6]); aZ[7] = fmaf(h, z1.w, aZ[7]);
            aN[0] = fmaf(h, n0.x, aN[0]); aN[1] = fmaf(h, n0.y, aN[1]);
            aN[2] = fmaf(h, n0.z, aN[2]); aN[3] = fmaf(h, n0.w, aN[3]);
            aN[4] = fmaf(h, n1.x, aN[4]); aN[5] = fmaf(h, n1.y, aN[5]);
            aN[6] = fmaf(h, n1.z, aN[6]); aN[7] = fmaf(h, n1.w, aN[7]);
        }
        // old h for this thread's units (read before overwrite)
        float4 ho0 = *(const float4*)(Hs + ty * 128 + 8 * tx);
        float4 ho1 = *(const float4*)(Hs + ty * 128 + 8 * tx + 4);
        float hold[8] = {ho0.x, ho0.y, ho0.z, ho0.w, ho1.x, ho1.y, ho1.z, ho1.w};
        const float* ig = g_IG + (row * KW + s) * 384;
        float4 i0 = *(const float4*)(ig + 8 * tx);
        float4 i1 = *(const float4*)(ig + 8 * tx + 4);
        float4 j0 = *(const float4*)(ig + 128 + 8 * tx);
        float4 j1 = *(const float4*)(ig + 128 + 8 * tx + 4);
        float4 m0 = *(const float4*)(ig + 256 + 8 * tx);
        float4 m1 = *(const float4*)(ig + 256 + 8 * tx + 4);
        float igr[8] = {i0.x, i0.y, i0.z, i0.w, i1.x, i1.y, i1.z, i1.w};
        float igz[8] = {j0.x, j0.y, j0.z, j0.w, j1.x, j1.y, j1.z, j1.w};
        float ign[8] = {m0.x, m0.y, m0.z, m0.w, m1.x, m1.y, m1.z, m1.w};
        float hn[8];
#pragma unroll
        for (int u = 0; u < 8; u++) {
            float r = 1.f / (1.f + expf(-(igr[u] + aR[u] + br[u])));
            float z = 1.f / (1.f + expf(-(igz[u] + aZ[u] + bz[u])));
            float n = tanhf(ign[u] + r * (aN[u] + bn[u]));
            hn[u] = (1.f - z) * n + z * hold[u];
        }
        __syncthreads();   // all GEMM reads of old Hs done
        *(float4*)(Hs + ty * 128 + 8 * tx)     = make_float4(hn[0], hn[1], hn[2], hn[3]);
        *(float4*)(Hs + ty * 128 + 8 * tx + 4) = make_float4(hn[4], hn[5], hn[6], hn[7]);
        __syncthreads();
    }
    *(float4*)(g_H1 + row * 128 + 8 * tx)     = *(const float4*)(Hs + ty * 128 + 8 * tx);
    *(float4*)(g_H1 + row * 128 + 8 * tx + 4) = *(const float4*)(Hs + ty * 128 + 8 * tx + 4);
}

// ---------------- 4) per-row scorer bases ----------------
__global__ __launch_bounds__(128) void posth_kernel(const float* __restrict__ Wt1,
                                                    const float* __restrict__ bt1,
                                                    const float* __restrict__ Wi1,
                                                    const float* __restrict__ bi1) {
    __shared__ float Xs[32][33];
    __shared__ float Ws[64][33];
    int row0 = blockIdx.x * 32;
    int h0 = blockIdx.y * 64;
    int tid = threadIdx.x, tx = tid & 15, ty = tid >> 4;
    float acc[4][4];

#pragma unroll
    for (int i = 0; i < 4; i++)
#pragma unroll
        for (int j = 0; j < 4; j++) acc[i][j] = 0.f;
    for (int k0 = 0; k0 < 256; k0 += 32) {
        for (int i = tid; i < 32 * 32; i += 128) {
            int r = i >> 5, k = i & 31, kg = k0 + k;
            Xs[r][k] = (kg < 128) ? g_last_text[(row0 + r) * 128 + kg]
                                  : g_H1[(row0 + r) * 128 + (kg - 128)];
        }
        for (int i = tid; i < 64 * 32; i += 128) {
            int r = i >> 5, k = i & 31, kg = k0 + k;
            Ws[r][k] = (kg < 128) ? Wt1[(h0 + r) * 384 + kg]
                                  : Wt1[(h0 + r) * 384 + 128 + kg];
        }
        __syncthreads();
#pragma unroll
        for (int k = 0; k < 32; k++) {
            float a[4], w[4];
#pragma unroll
            for (int i = 0; i < 4; i++) a[i] = Xs[ty + 8 * i][k];
#pragma unroll
            for (int j = 0; j < 4; j++) w[j] = Ws[tx + 16 * j][k];
#pragma unroll
            for (int i = 0; i < 4; i++)
#pragma unroll
                for (int j = 0; j < 4; j++) acc[i][j] = fmaf(a[i], w[j], acc[i][j]);
        }
        __syncthreads();
    }
#pragma unroll
    for (int j = 0; j < 4; j++) {
        int h = h0 + tx + 16 * j;
        float bv = bt1[h];
#pragma unroll
        for (int i = 0; i < 4; i++)
            g_base_t[(row0 + ty + 8 * i) * NH + h] = acc[i][j] + bv;
    }
    __syncthreads();

#pragma unroll
    for (int i = 0; i < 4; i++)
#pragma unroll
        for (int j = 0; j < 4; j++) acc[i][j] = 0.f;
    for (int k0 = 0; k0 < 192; k0 += 32) {
        for (int i = tid; i < 32 * 32; i += 128) {
            int r = i >> 5, k = i & 31, kg = k0 + k;
            Xs[r][k] = (kg < 64) ? g_last_id[(row0 + r) * 64 + kg]
                                 : g_H1[(row0 + r) * 128 + (kg - 64)];
        }
        for (int i = tid; i < 64 * 32; i += 128) {
            int r = i >> 5, k = i & 31, kg = k0 + k;
            Ws[r][k] = (kg < 64) ? Wi1[(h0 + r) * 256 + kg]
                                 : Wi1[(h0 + r) * 256 + 64 + kg];
        }
        __syncthreads();
#pragma unroll
        for (int k = 0; k < 32; k++) {
            float a[4], w[4];
#pragma unroll
            for (int i = 0; i < 4; i++) a[i] = Xs[ty + 8 * i][k];
#pragma unroll
            for (int j = 0; j < 4; j++) w[j] = Ws[tx + 16 * j][k];
#pragma unroll
            for (int i = 0; i < 4; i++)
#pragma unroll
                for (int j = 0; j < 4; j++) acc[i][j] = fmaf(a[i], w[j], acc[i][j]);
        }
        __syncthreads();
    }
#pragma unroll
    for (int j = 0; j < 4; j++) {
        int h = h0 + tx + 16 * j;
        float bv = bi1[h];
#pragma unroll
        for (int i = 0; i < 4; i++)
            g_base_i[(row0 + ty + 8 * i) * NH + h] = acc[i][j] + bv;
    }
}

// ---------------- 5) mixture gate alpha ----------------
__global__ void alpha_kernel(const float* __restrict__ Wa1, const float* __restrict__ ba1,
                             const float* __restrict__ Wa2, const float* __restrict__ ba2) {
    __shared__ float hs[128];
    __shared__ float a1s[64];
    int b = blockIdx.x, t = threadIdx.x;   // 64 threads
    hs[t]      = g_H1[b * 128 + t];
    hs[64 + t] = g_H1[b * 128 + 64 + t];
    __syncthreads();
    float s = ba1[t];
#pragma unroll 4
    for (int d = 0; d < 128; d++) s = fmaf(Wa1[t * 128 + d], hs[d], s);
    a1s[t] = fmaxf(s, 0.f);
    __syncthreads();
    if (t == 0) {
        float lg[3];
#pragma unroll
        for (int g = 0; g < 3; g++) {
            float x = ba2[g];
            for (int d = 0; d < 64; d++) x = fmaf(Wa2[g * 64 + d], a1s[d], x);
            lg[g] = x;
        }
        float m = fmaxf(lg[0], fmaxf(lg[1], lg[2]));
        float e0 = expf(lg[0] - m), e1 = expf(lg[1] - m), e2 = expf(lg[2] - m);
        float ss = e0 + e1 + e2;
        g_alpha[b * 3 + 0] = e0 / ss;
        g_alpha[b * 3 + 1] = e1 / ss;
        g_alpha[b * 3 + 2] = e2 / ss;
    }
}

// ---------------- 6) bulk scorer GEMM with packed f32x2 FMA ----------------
// logits[row] = b2 + sum_h relu(base[b][h] + sum_k A[row,k]*W[h,k]) * w2[h]
template <int KD, int WS, bool TEXT>
__global__ __launch_bounds__(256, 2) void scorer2(const float* __restrict__ A,
                                                  const float* __restrict__ W,
                                                  const float* __restrict__ w2,
                                                  const float* __restrict__ b2p) {
    __shared__ float As[128][33];
    __shared__ __align__(16) float Wk[32][134];   // k-major, unit pairs contiguous
    const float* base = TEXT ? g_base_t : g_base_i;
    float* outL       = TEXT ? g_logits_t : g_logits_i;
    int row0 = blockIdx.x * 128;
    int tid = threadIdx.x, tx = tid & 15, ty = tid >> 4;

    ull acc[8][4];
#pragma unroll
    for (int i = 0; i < 8; i++)
#pragma unroll
        for (int j = 0; j < 4; j++) acc[i][j] = 0ull;

    for (int kt = 0; kt < KD; kt += 32) {
        for (int i = tid; i < 128 * 32; i += 256)
            As[i >> 5][i & 31] = A[(row0 + (i >> 5)) * KD + kt + (i & 31)];
        for (int i = tid; i < 128 * 32; i += 256) {
            int j = i >> 5, k = i & 31;
            Wk[k][j] = W[j * WS + kt + k];
        }
        __syncthreads();
#pragma unroll 2
        for (int k = 0; k < 32; k++) {
            ull aa[8];
#pragma unroll
            for (int i = 0; i < 8; i++) {
                float a = As[ty + 16 * i][k];
                asm("mov.b64 %0, {%1, %1};" : "=l"(aa[i]) : "f"(a));
            }
            ull ww[4];
#pragma unroll
            for (int jj = 0; jj < 4; jj++)
                ww[jj] = *(const ull*)&Wk[k][2 * (tx + 16 * jj)];
#pragma unroll
            for (int i = 0; i < 8; i++)
#pragma unroll
                for (int jj = 0; jj < 4; jj++)
                    asm("fma.rn.f32x2 %0, %1, %2, %0;"
                        : "+l"(acc[i][jj]) : "l"(aa[i]), "l"(ww[jj]));
        }
        __syncthreads();
    }

    float b2 = b2p[0];
    float w2a[4], w2b[4];
#pragma unroll
    for (int jj = 0; jj < 4; jj++) {
        w2a[jj] = w2[2 * (tx + 16 * jj)];
        w2b[jj] = w2[2 * (tx + 16 * jj) + 1];
    }
#pragma unroll
    for (int i = 0; i < 8; i++) {
        int rowg = row0 + ty + 16 * i;
        int b = rowg / CC;
        const float* bp = base + b * NH;
        float p = 0.f;
#pragma unroll
        for (int jj = 0; jj < 4; jj++) {
            int u = 2 * (tx + 16 * jj);
            float x0, x1;
            asm("mov.b64 {%0, %1}, %2;" : "=f"(x0), "=f"(x1) : "l"(acc[i][jj]));
            x0 = fmaxf(x0 + bp[u], 0.f);
            x1 = fmaxf(x1 + bp[u + 1], 0.f);
            p = fmaf(x0, w2a[jj], p);
            p = fmaf(x1, w2b[jj], p);
        }
        p += __shfl_xor_sync(0xffffffff, p, 8);
        p += __shfl_xor_sync(0xffffffff, p, 4);
        p += __shfl_xor_sync(0xffffffff, p, 2);
        p += __shfl_xor_sync(0xffffffff, p, 1);
        if (tx == 0) outL[rowg] = p + b2;
    }
}

// ---------------- 7) three softmaxes + mixture + normalize ----------------
__device__ __forceinline__ float blkmax(float v, float* sm) {
    int t = threadIdx.x;
    sm[t] = v; __syncthreads();
#pragma unroll
    for (int s = 64; s > 0; s >>= 1) {
        if (t < s) sm[t] = fmaxf(sm[t], sm[t + s]);
        __syncthreads();
    }
    float r = sm[0]; __syncthreads();
    return r;
}
__device__ __forceinline__ float blksum(float v, float* sm) {
    int t = threadIdx.x;
    sm[t] = v; __syncthreads();
#pragma unroll
    for (int s = 64; s > 0; s >>= 1) {
        if (t < s) sm[t] = sm[t] + sm[t + s];
        __syncthreads();
    }
    float r = sm[0]; __syncthreads();
    return r;
}

__global__ void finalize_kernel(const int* __restrict__ cand_ids,
                                const float* __restrict__ co_table,
                                const float* __restrict__ beta_c,
                                const float* __restrict__ logT_c,
                                const float* __restrict__ logT_t,
                                const float* __restrict__ logT_id,
                                float* __restrict__ out) {
    __shared__ float sm[128];
    int b = blockIdx.x, t = threadIdx.x;   // 128 threads
    float itc = expf(-logT_c[0]) * beta_c[0];
    float itt = expf(-logT_t[0]);
    float iti = expf(-logT_id[0]);
    float vc = -1e30f, vt = -1e30f, vi = -1e30f;
    if (t < CC) {
        int cid = cand_ids[b * CC + t];
        vc = co_table[g_last_item[b] * VV + cid] * itc;
        vt = g_logits_t[b * CC + t] * itt;
        vi = g_logits_i[b * CC + t] * iti;
    }
    float mc = blkmax(vc, sm);
    float mt = blkmax(vt, sm);
    float mi = blkmax(vi, sm);
    float ec = (t < CC) ? expf(vc - mc) : 0.f;
    float et = (t < CC) ? expf(vt - mt) : 0.f;
    float ei = (t < CC) ? expf(vi - mi) : 0.f;
    float sc = blksum(ec, sm);
    float st = blksum(et, sm);
    float si = blksum(ei, sm);
    float a0 = g_alpha[b * 3 + 0], a1 = g_alpha[b * 3 + 1], a2 = g_alpha[b * 3 + 2];
    float mix = 0.f;
    if (t < CC) {
        mix = a0 * (ec / sc) + a1 * (et / st) + a2 * (ei / si) + (1.0f / CC);
        mix = fmaxf(mix, 1e-12f);
    }
    float tot = blksum(mix, sm);
    if (t < CC) out[b * CC + t] = mix / tot;
}

// ---------------- launch ----------------
extern "C" void kernel_launch(void* const* d_in, const int* in_sizes, int n_in,
                              void* d_out, int out_size) {
    const int*   seq_items = (const int*)d_in[0];
    const float* seq_id    = (const float*)d_in[1];
    const float* seq_txt   = (const float*)d_in[2];
    const int*   lengths   = (const int*)d_in[3];
    const int*   cand_ids  = (const int*)d_in[4];
    const float* cand_id_e = (const float*)d_in[5];
    const float* cand_tx_e = (const float*)d_in[6];
    const float* co_table  = (const float*)d_in[7];
    const float* W_ih = (const float*)d_in[8];
    const float* W_hh = (const float*)d_in[9];
    const float* b_ih = (const float*)d_in[10];
    const float* b_hh = (const float*)d_in[11];
    const float* Wt1  = (const float*)d_in[12];
    const float* bt1  = (const float*)d_in[13];
    const float* Wt2  = (const float*)d_in[14];
    const float* bt2  = (const float*)d_in[15];
    const float* Wi1  = (const float*)d_in[16];
    const float* bi1  = (const float*)d_in[17];
    const float* Wi2  = (const float*)d_in[18];
    const float* bi2  = (const float*)d_in[19];
    const float* Wa1  = (const float*)d_in[20];
    const float* ba1  = (const float*)d_in[21];
    const float* Wa2  = (const float*)d_in[22];
    const float* ba2  = (const float*)d_in[23];
    // d_in[24] (Wstab) is dead: softmax of a row-constant vector is uniform.
    const float* beta_c  = (const float*)d_in[25];
    const float* logT_c  = (const float*)d_in[26];
    const float* logT_t  = (const float*)d_in[27];
    const float* logT_id = (const float*)d_in[28];
    float* out = (float*)d_out;

    const int GRU_SMEM = (128 * 384 + 16 * 128) * 4;   // 204800 B
    cudaFuncSetAttribute(gru_fused, cudaFuncAttributeMaxDynamicSharedMemorySize, GRU_SMEM);

    prep_kernel<<<BB, 192>>>(seq_items, seq_id, seq_txt, lengths);
    transpose_whh<<<dim3(12, 4), dim3(32, 8)>>>(W_hh);
    ih_gemm<<<dim3(80, 6), 256>>>(W_ih, b_ih);
    gru_fused<<<128, 256, GRU_SMEM>>>(b_hh);
    posth_kernel<<<dim3(64, 2), 128>>>(Wt1, bt1, Wi1, bi1);
    alpha_kernel<<<BB, 64>>>(Wa1, ba1, Wa2, ba2);
    scorer2<128, 384, true><<<1600, 256>>>(cand_tx_e, Wt1 + 128, Wt2, bt2);
    scorer2<64, 256, false><<<1600, 256>>>(cand_id_e, Wi1 + 64, Wi2, bi2);
    finalize_kernel<<<BB, 128>>>(cand_ids, co_table, beta_c, logT_c, logT_t, logT_id, out);
}

// round 11
// speedup vs baseline: 1.1122x; 1.0133x over previous
#include <cuda_runtime.h>
#include <math.h>

#define BB 2048
#define LL 200
#define CC 100
#define D_ID 64
#define D_TXT 128
#define D_CTX 128
#define KW 5
#define VV 2000
#define D_IN 192
#define NH 128

// ---------------- scratch (static device arrays; no allocation) ----------------
__device__ __align__(16) float g_XK[BB * KW * D_IN];
__device__ __align__(16) float g_IG[BB * KW * 3 * D_CTX];
__device__ __align__(16) float g_WhhT[D_CTX * 3 * D_CTX];
__device__ __align__(16) float g_H1[BB * D_CTX];
__device__ __align__(16) float g_last_text[BB * D_TXT];
__device__ __align__(16) float g_last_id[BB * D_ID];
__device__ int   g_last_item[BB];
__device__ __align__(16) float g_base_t[BB * NH];
__device__ __align__(16) float g_base_i[BB * NH];
__device__ float g_alpha[BB * 3];
__device__ float g_logits_t[BB * CC];
__device__ float g_logits_i[BB * CC];

// ---------------- 1) gather window + last-step features ----------------
__global__ void prep_kernel(const int* __restrict__ seq_items,
                            const float* __restrict__ seq_id,
                            const float* __restrict__ seq_txt,
                            const int* __restrict__ lengths) {
    int b = blockIdx.x, t = threadIdx.x;     // 192 threads
    int len = lengths[b];
    int start = len - KW, last = len - 1;
#pragma unroll
    for (int k = 0; k < KW; k++) {
        float v;
        if (t < D_ID) v = seq_id[(b * LL + start + k) * D_ID + t];
        else          v = seq_txt[(b * LL + start + k) * D_TXT + (t - D_ID)];
        g_XK[(b * KW + k) * D_IN + t] = v;
    }
    if (t < D_ID)  g_last_id[b * D_ID + t]   = seq_id[(b * LL + last) * D_ID + t];
    if (t < D_TXT) g_last_text[b * D_TXT + t] = seq_txt[(b * LL + last) * D_TXT + t];
    if (t == 0)    g_last_item[b] = seq_items[b * LL + last];
}

// ---------------- 1b) transpose W_hh [384][128] -> g_WhhT [128][384] ----------------
__global__ void transpose_whh(const float* __restrict__ Whh) {
    __shared__ float t[32][33];
    int bx = blockIdx.x, by = blockIdx.y;
    int x = threadIdx.x, y = threadIdx.y;    // 32 x 8
#pragma unroll
    for (int i = 0; i < 32; i += 8)
        t[y + i][x] = Whh[(bx * 32 + y + i) * D_CTX + by * 32 + x];
    __syncthreads();
#pragma unroll
    for (int i = 0; i < 32; i += 8)
        g_WhhT[(by * 32 + y + i) * 384 + bx * 32 + x] = t[x][y + i];
}

// ---------------- 2) i-gates GEMM: IG[10240,384] = XK @ W_ih.T + b_ih ----------------
__global__ __launch_bounds__(256, 2) void ih_gemm(const float* __restrict__ Wih,
                                                  const float* __restrict__ bih) {
    __shared__ float As[128][33];
    __shared__ float Bs[64][33];
    int row0 = blockIdx.x * 128;
    int col0 = blockIdx.y * 64;
    int tid = threadIdx.x, tx = tid & 15, ty = tid >> 4;
    float acc[8][4];
#pragma unroll
    for (int i = 0; i < 8; i++)
#pragma unroll
        for (int j = 0; j < 4; j++) acc[i][j] = 0.f;

    for (int k0 = 0; k0 < D_IN; k0 += 32) {
        for (int i = tid; i < 128 * 32; i += 256)
            As[i >> 5][i & 31] = g_XK[(row0 + (i >> 5)) * D_IN + k0 + (i & 31)];
        for (int i = tid; i < 64 * 32; i += 256)
            Bs[i >> 5][i & 31] = Wih[(col0 + (i >> 5)) * D_IN + k0 + (i & 31)];
        __syncthreads();
#pragma unroll
        for (int k = 0; k < 32; k++) {
            float a[8], w[4];
#pragma unroll
            for (int i = 0; i < 8; i++) a[i] = As[ty + 16 * i][k];
#pragma unroll
            for (int j = 0; j < 4; j++) w[j] = Bs[tx + 16 * j][k];
#pragma unroll
            for (int i = 0; i < 8; i++)
#pragma unroll
                for (int j = 0; j < 4; j++) acc[i][j] = fmaf(a[i], w[j], acc[i][j]);
        }
        __syncthreads();
    }
#pragma unroll
    for (int j = 0; j < 4; j++) {
        int col = col0 + tx + 16 * j;
        float bv = bih[col];
#pragma unroll
        for (int i = 0; i < 8; i++)
            g_IG[(row0 + ty + 16 * i) * (3 * D_CTX) + col] = acc[i][j] + bv;
    }
}

// ---------------- 3) fused GRU: all 5 steps, high arithmetic intensity ----------------
// 128 blocks x 16 rows; 192 threads: ug=tid%48 -> gate+8 units, rg=tid/48 -> 4 rows
extern __shared__ float smem_dyn[];
__global__ __launch_bounds__(192) void gru_fused2(const float* __restrict__ bhh) {
    float* Ws = smem_dyn;                   // [128][384] k-major
    float* Hs = smem_dyn + 49152;           // [16][128]
    float* Sm = smem_dyn + 49152 + 2048;    // [3][16][128] gate partial sums
    int tid = threadIdx.x;
    int ug = tid % 48, rg = tid / 48;
    int row0 = blockIdx.x * 16;
    {
        const float4* src = (const float4*)g_WhhT;
        float4* dst = (float4*)Ws;
        for (int i = tid; i < 12288; i += 192) dst[i] = src[i];
    }
    for (int i = tid; i < 2048; i += 192) Hs[i] = 0.f;
    __syncthreads();

    int gate = ug >> 4;
    int j0 = (ug & 15) * 8;
    for (int s = 0; s < KW; s++) {
        float acc[4][8];
#pragma unroll
        for (int i = 0; i < 4; i++)
#pragma unroll
            for (int u = 0; u < 8; u++) acc[i][u] = 0.f;
#pragma unroll 2
        for (int k = 0; k < 128; k++) {
            float4 w0 = *(const float4*)(Ws + k * 384 + ug * 8);
            float4 w1 = *(const float4*)(Ws + k * 384 + ug * 8 + 4);
            float h0 = Hs[(rg * 4 + 0) * 128 + k];
            float h1 = Hs[(rg * 4 + 1) * 128 + k];
            float h2 = Hs[(rg * 4 + 2) * 128 + k];
            float h3 = Hs[(rg * 4 + 3) * 128 + k];
            float wv[8] = {w0.x, w0.y, w0.z, w0.w, w1.x, w1.y, w1.z, w1.w};
#pragma unroll
            for (int u = 0; u < 8; u++) {
                acc[0][u] = fmaf(h0, wv[u], acc[0][u]);
                acc[1][u] = fmaf(h1, wv[u], acc[1][u]);
                acc[2][u] = fmaf(h2, wv[u], acc[2][u]);
                acc[3][u] = fmaf(h3, wv[u], acc[3][u]);
            }
        }
#pragma unroll
        for (int i = 0; i < 4; i++) {
            float* d = Sm + gate * 2048 + (rg * 4 + i) * 128 + j0;
            *(float4*)d       = make_float4(acc[i][0], acc[i][1], acc[i][2], acc[i][3]);
            *(float4*)(d + 4) = make_float4(acc[i][4], acc[i][5], acc[i][6], acc[i][7]);
        }
        __syncthreads();
        for (int idx = tid; idx < 2048; idx += 192) {
            int row = idx >> 7, j = idx & 127;
            float rs = Sm[idx];
            float zs = Sm[2048 + idx];
            float ns = Sm[4096 + idx];
            const float* ig = g_IG + (((row0 + row) * KW + s) * 384);
            float r = 1.f / (1.f + expf(-(ig[j]       + rs + bhh[j])));
            float z = 1.f / (1.f + expf(-(ig[128 + j] + zs + bhh[128 + j])));
            float n = tanhf(ig[256 + j] + r * (ns + bhh[256 + j]));
            float hn = (1.f - z) * n + z * Hs[idx];
            Hs[idx] = hn;
            if (s == KW - 1) g_H1[(row0 + row) * 128 + j] = hn;
        }
        __syncthreads();
    }
}

// ---------------- 4) per-row scorer bases ----------------
__global__ __launch_bounds__(128) void posth_kernel(const float* __restrict__ Wt1,
                                                    const float* __restrict__ bt1,
                                                    const float* __restrict__ Wi1,
                                                    const float* __restrict__ bi1) {
    __shared__ float Xs[32][33];
    __shared__ float Ws[64][33];
    int row0 = blockIdx.x * 32;
    int h0 = blockIdx.y * 64;
    int tid = threadIdx.x, tx = tid & 15, ty = tid >> 4;
    float acc[4][4];

#pragma unroll
    for (int i = 0; i < 4; i++)
#pragma unroll
        for (int j = 0; j < 4; j++) acc[i][j] = 0.f;
    for (int k0 = 0; k0 < 256; k0 += 32) {
        for (int i = tid; i < 32 * 32; i += 128) {
            int r = i >> 5, k = i & 31, kg = k0 + k;
            Xs[r][k] = (kg < 128) ? g_last_text[(row0 + r) * 128 + kg]
                                  : g_H1[(row0 + r) * 128 + (kg - 128)];
        }
        for (int i = tid; i < 64 * 32; i += 128) {
            int r = i >> 5, k = i & 31, kg = k0 + k;
            Ws[r][k] = (kg < 128) ? Wt1[(h0 + r) * 384 + kg]
                                  : Wt1[(h0 + r) * 384 + 128 + kg];
        }
        __syncthreads();
#pragma unroll
        for (int k = 0; k < 32; k++) {
            float a[4], w[4];
#pragma unroll
            for (int i = 0; i < 4; i++) a[i] = Xs[ty + 8 * i][k];
#pragma unroll
            for (int j = 0; j < 4; j++) w[j] = Ws[tx + 16 * j][k];
#pragma unroll
            for (int i = 0; i < 4; i++)
#pragma unroll
                for (int j = 0; j < 4; j++) acc[i][j] = fmaf(a[i], w[j], acc[i][j]);
        }
        __syncthreads();
    }
#pragma unroll
    for (int j = 0; j < 4; j++) {
        int h = h0 + tx + 16 * j;
        float bv = bt1[h];
#pragma unroll
        for (int i = 0; i < 4; i++)
            g_base_t[(row0 + ty + 8 * i) * NH + h] = acc[i][j] + bv;
    }
    __syncthreads();

#pragma unroll
    for (int i = 0; i < 4; i++)
#pragma unroll
        for (int j = 0; j < 4; j++) acc[i][j] = 0.f;
    for (int k0 = 0; k0 < 192; k0 += 32) {
        for (int i = tid; i < 32 * 32; i += 128) {
            int r = i >> 5, k = i & 31, kg = k0 + k;
            Xs[r][k] = (kg < 64) ? g_last_id[(row0 + r) * 64 + kg]
                                 : g_H1[(row0 + r) * 128 + (kg - 64)];
        }
        for (int i = tid; i < 64 * 32; i += 128) {
            int r = i >> 5, k = i & 31, kg = k0 + k;
            Ws[r][k] = (kg < 64) ? Wi1[(h0 + r) * 256 + kg]
                                 : Wi1[(h0 + r) * 256 + 64 + kg];
        }
        __syncthreads();
#pragma unroll
        for (int k = 0; k < 32; k++) {
            float a[4], w[4];
#pragma unroll
            for (int i = 0; i < 4; i++) a[i] = Xs[ty + 8 * i][k];
#pragma unroll
            for (int j = 0; j < 4; j++) w[j] = Ws[tx + 16 * j][k];
#pragma unroll
            for (int i = 0; i < 4; i++)
#pragma unroll
                for (int j = 0; j < 4; j++) acc[i][j] = fmaf(a[i], w[j], acc[i][j]);
        }
        __syncthreads();
    }
#pragma unroll
    for (int j = 0; j < 4; j++) {
        int h = h0 + tx + 16 * j;
        float bv = bi1[h];
#pragma unroll
        for (int i = 0; i < 4; i++)
            g_base_i[(row0 + ty + 8 * i) * NH + h] = acc[i][j] + bv;
    }
}

// ---------------- 5) mixture gate alpha ----------------
__global__ void alpha_kernel(const float* __restrict__ Wa1, const float* __restrict__ ba1,
                             const float* __restrict__ Wa2, const float* __restrict__ ba2) {
    __shared__ float hs[128];
    __shared__ float a1s[64];
    int b = blockIdx.x, t = threadIdx.x;   // 64 threads
    hs[t]      = g_H1[b * 128 + t];
    hs[64 + t] = g_H1[b * 128 + 64 + t];
    __syncthreads();
    float s = ba1[t];
#pragma unroll 4
    for (int d = 0; d < 128; d++) s = fmaf(Wa1[t * 128 + d], hs[d], s);
    a1s[t] = fmaxf(s, 0.f);
    __syncthreads();
    if (t == 0) {
        float lg[3];
#pragma unroll
        for (int g = 0; g < 3; g++) {
            float x = ba2[g];
            for (int d = 0; d < 64; d++) x = fmaf(Wa2[g * 64 + d], a1s[d], x);
            lg[g] = x;
        }
        float m = fmaxf(lg[0], fmaxf(lg[1], lg[2]));
        float e0 = expf(lg[0] - m), e1 = expf(lg[1] - m), e2 = expf(lg[2] - m);
        float ss = e0 + e1 + e2;
        g_alpha[b * 3 + 0] = e0 / ss;
        g_alpha[b * 3 + 1] = e1 / ss;
        g_alpha[b * 3 + 2] = e2 / ss;
    }
}

// ---------------- 6) bulk scorer GEMM + relu + dot(w2) epilogue (fp32, benched-good) ----------------
// logits[row] = b2 + sum_h relu(base[b][h] + sum_k A[row,k]*W[h,k]) * w2[h]
template <int KD, int WS, bool TEXT>
__global__ __launch_bounds__(256, 2) void scorer_kernel(const float* __restrict__ A,
                                                        const float* __restrict__ W,
                                                        const float* __restrict__ w2,
                                                        const float* __restrict__ b2p) {
    __shared__ float As[128][33];
    __shared__ float Ws[128][33];
    const float* base = TEXT ? g_base_t : g_base_i;
    float* outL       = TEXT ? g_logits_t : g_logits_i;
    int row0 = blockIdx.x * 128;
    int tid = threadIdx.x, tx = tid & 15, ty = tid >> 4;
    float acc[8][8];
#pragma unroll
    for (int i = 0; i < 8; i++)
#pragma unroll
        for (int j = 0; j < 8; j++) acc[i][j] = 0.f;

    for (int k0 = 0; k0 < KD; k0 += 32) {
        for (int i = tid; i < 128 * 32; i += 256)
            As[i >> 5][i & 31] = A[(row0 + (i >> 5)) * KD + k0 + (i & 31)];
        for (int i = tid; i < 128 * 32; i += 256)
            Ws[i >> 5][i & 31] = W[(i >> 5) * WS + k0 + (i & 31)];
        __syncthreads();
#pragma unroll
        for (int k = 0; k < 32; k++) {
            float a[8], w[8];
#pragma unroll
            for (int i = 0; i < 8; i++) a[i] = As[ty + 16 * i][k];
#pragma unroll
            for (int j = 0; j < 8; j++) w[j] = Ws[tx + 16 * j][k];
#pragma unroll
            for (int i = 0; i < 8; i++)
#pragma unroll
                for (int j = 0; j < 8; j++) acc[i][j] = fmaf(a[i], w[j], acc[i][j]);
        }
        __syncthreads();
    }
    float b2 = b2p[0];
    float w2r[8];
#pragma unroll
    for (int j = 0; j < 8; j++) w2r[j] = w2[tx + 16 * j];
#pragma unroll
    for (int i = 0; i < 8; i++) {
        int row = row0 + ty + 16 * i;
        int b = row / CC;
        const float* bp = base + b * NH;
        float p = 0.f;
#pragma unroll
        for (int j = 0; j < 8; j++) {
            float v = acc[i][j] + bp[tx + 16 * j];
            v = fmaxf(v, 0.f);
            p = fmaf(v, w2r[j], p);
        }
        p += __shfl_xor_sync(0xffffffff, p, 8);
        p += __shfl_xor_sync(0xffffffff, p, 4);
        p += __shfl_xor_sync(0xffffffff, p, 2);
        p += __shfl_xor_sync(0xffffffff, p, 1);
        if (tx == 0) outL[row] = p + b2;
    }
}

// ---------------- 7) three softmaxes + mixture + normalize ----------------
__device__ __forceinline__ float blkmax(float v, float* sm) {
    int t = threadIdx.x;
    sm[t] = v; __syncthreads();
#pragma unroll
    for (int s = 64; s > 0; s >>= 1) {
        if (t < s) sm[t] = fmaxf(sm[t], sm[t + s]);
        __syncthreads();
    }
    float r = sm[0]; __syncthreads();
    return r;
}
__device__ __forceinline__ float blksum(float v, float* sm) {
    int t = threadIdx.x;
    sm[t] = v; __syncthreads();
#pragma unroll
    for (int s = 64; s > 0; s >>= 1) {
        if (t < s) sm[t] = sm[t] + sm[t + s];
        __syncthreads();
    }
    float r = sm[0]; __syncthreads();
    return r;
}

__global__ void finalize_kernel(const int* __restrict__ cand_ids,
                                const float* __restrict__ co_table,
                                const float* __restrict__ beta_c,
                                const float* __restrict__ logT_c,
                                const float* __restrict__ logT_t,
                                const float* __restrict__ logT_id,
                                float* __restrict__ out) {
    __shared__ float sm[128];
    int b = blockIdx.x, t = threadIdx.x;   // 128 threads
    float itc = expf(-logT_c[0]) * beta_c[0];
    float itt = expf(-logT_t[0]);
    float iti = expf(-logT_id[0]);
    float vc = -1e30f, vt = -1e30f, vi = -1e30f;
    if (t < CC) {
        int cid = cand_ids[b * CC + t];
        vc = co_table[g_last_item[b] * VV + cid] * itc;
        vt = g_logits_t[b * CC + t] * itt;
        vi = g_logits_i[b * CC + t] * iti;
    }
    float mc = blkmax(vc, sm);
    float mt = blkmax(vt, sm);
    float mi = blkmax(vi, sm);
    float ec = (t < CC) ? expf(vc - mc) : 0.f;
    float et = (t < CC) ? expf(vt - mt) : 0.f;
    float ei = (t < CC) ? expf(vi - mi) : 0.f;
    float sc = blksum(ec, sm);
    float st = blksum(et, sm);
    float si = blksum(ei, sm);
    float a0 = g_alpha[b * 3 + 0], a1 = g_alpha[b * 3 + 1], a2 = g_alpha[b * 3 + 2];
    float mix = 0.f;
    if (t < CC) {
        // P_stable is softmax of a row-constant vector => exactly 1/C
        mix = a0 * (ec / sc) + a1 * (et / st) + a2 * (ei / si) + (1.0f / CC);
        mix = fmaxf(mix, 1e-12f);
    }
    float tot = blksum(mix, sm);
    if (t < CC) out[b * CC + t] = mix / tot;
}

// ---------------- launch ----------------
extern "C" void kernel_launch(void* const* d_in, const int* in_sizes, int n_in,
                              void* d_out, int out_size) {
    const int*   seq_items = (const int*)d_in[0];
    const float* seq_id    = (const float*)d_in[1];
    const float* seq_txt   = (const float*)d_in[2];
    const int*   lengths   = (const int*)d_in[3];
    const int*   cand_ids  = (const int*)d_in[4];
    const float* cand_id_e = (const float*)d_in[5];
    const float* cand_tx_e = (const float*)d_in[6];
    const float* co_table  = (const float*)d_in[7];
    const float* W_ih = (const float*)d_in[8];
    const float* W_hh = (const float*)d_in[9];
    const float* b_ih = (const float*)d_in[10];
    const float* b_hh = (const float*)d_in[11];
    const float* Wt1  = (const float*)d_in[12];
    const float* bt1  = (const float*)d_in[13];
    const float* Wt2  = (const float*)d_in[14];
    const float* bt2  = (const float*)d_in[15];
    const float* Wi1  = (const float*)d_in[16];
    const float* bi1  = (const float*)d_in[17];
    const float* Wi2  = (const float*)d_in[18];
    const float* bi2  = (const float*)d_in[19];
    const float* Wa1  = (const float*)d_in[20];
    const float* ba1  = (const float*)d_in[21];
    const float* Wa2  = (const float*)d_in[22];
    const float* ba2  = (const float*)d_in[23];
    // d_in[24] (Wstab) is dead: softmax of a row-constant vector is uniform.
    const float* beta_c  = (const float*)d_in[25];
    const float* logT_c  = (const float*)d_in[26];
    const float* logT_t  = (const float*)d_in[27];
    const float* logT_id = (const float*)d_in[28];
    float* out = (float*)d_out;

    const int GRU_SMEM = (49152 + 2048 + 6144) * 4;   // 229376 B
    cudaFuncSetAttribute(gru_fused2, cudaFuncAttributeMaxDynamicSharedMemorySize, GRU_SMEM);

    prep_kernel<<<BB, 192>>>(seq_items, seq_id, seq_txt, lengths);
    transpose_whh<<<dim3(12, 4), dim3(32, 8)>>>(W_hh);
    ih_gemm<<<dim3(80, 6), 256>>>(W_ih, b_ih);
    gru_fused2<<<128, 192, GRU_SMEM>>>(b_hh);
    posth_kernel<<<dim3(64, 2), 128>>>(Wt1, bt1, Wi1, bi1);
    alpha_kernel<<<BB, 64>>>(Wa1, ba1, Wa2, ba2);
    scorer_kernel<128, 384, true><<<1600, 256>>>(cand_tx_e, Wt1 + 128, Wt2, bt2);
    scorer_kernel<64, 256, false><<<1600, 256>>>(cand_id_e, Wi1 + 64, Wi2, bi2);
    finalize_kernel<<<BB, 128>>>(cand_ids, co_table, beta_c, logT_c, logT_t, logT_id, out);
}